// round 1
// baseline (speedup 1.0000x reference)
#include <cuda_runtime.h>
#include <math.h>

#define D_  1024
#define H_  16
#define HD_ 64
#define F_  2816
#define A_  64
#define P_  30
#define NB_ 32
#define B_  4
#define L_  1024
#define LK_ 1054            // P_ + L_
#define M_  4096            // B_ * L_

// ---------------- scratch (device globals; no runtime allocation) ----------------
__device__ float g_xn[M_ * D_];
__device__ float g_q [M_ * D_];
__device__ float g_kc[B_ * LK_ * D_];
__device__ float g_vc[B_ * LK_ * D_];
__device__ float g_o [M_ * D_];
__device__ float g_x [M_ * D_];
__device__ float g_y [M_ * D_];
__device__ float g_h0[(size_t)M_ * F_];
__device__ float g_h1[(size_t)M_ * F_];
__device__ float g_az[B_ * L_ * A_];
__device__ float g_bt[H_ * L_];

// ---------------- helpers ----------------
__device__ __forceinline__ float gelu_f(float x) {
    const float c = 0.7978845608028654f;       // sqrt(2/pi)
    float t = tanhf(c * (x + 0.044715f * x * x * x));
    return 0.5f * x * (1.0f + t);
}

// ---------------- rmsnorm: one block per row, 256 threads, D=1024 ----------------
__global__ void rmsnorm_kernel(const float* __restrict__ x,
                               const float* __restrict__ sc,
                               float* __restrict__ out) {
    int row = blockIdx.x;
    int t = threadIdx.x;
    const float4* xr = (const float4*)(x + (size_t)row * D_);
    float4 v = xr[t];
    float ss = v.x * v.x + v.y * v.y + v.z * v.z + v.w * v.w;
    #pragma unroll
    for (int o = 16; o; o >>= 1) ss += __shfl_xor_sync(0xffffffffu, ss, o);
    __shared__ float sred[8];
    if ((t & 31) == 0) sred[t >> 5] = ss;
    __syncthreads();
    if (t < 8) {
        float s2 = sred[t];
        #pragma unroll
        for (int o = 4; o; o >>= 1) s2 += __shfl_xor_sync(0xffu, s2, o);
        if (t == 0) sred[0] = s2;
    }
    __syncthreads();
    float inv = rsqrtf(sred[0] * (1.0f / D_) + 1e-6f);
    float4 sv = ((const float4*)sc)[t];
    float4 ov = make_float4(v.x * inv * sv.x, v.y * inv * sv.y,
                            v.z * inv * sv.z, v.w * inv * sv.w);
    ((float4*)(out + (size_t)row * D_))[t] = ov;
}

// ---------------- generic SGEMM: C = alpha*A*B (+bias)(gelu)(+residual)(+=C) ----------------
// Row-major A[M,K], B[K,N], C rows optionally remapped for KV prefix padding.
// Batched via blockIdx.z with explicit strides.
#define GBM 128
#define GBN 128
#define GBK 8

__global__ __launch_bounds__(256, 2)
void sgemm_kernel(const float* __restrict__ A, const float* __restrict__ Bm,
                  float* __restrict__ C, int M, int N, int K,
                  float alpha,
                  const float* __restrict__ bias,
                  const float* __restrict__ residual,
                  int do_gelu, int accumulate, int kv_pad, int seg_rows,
                  long long sA, long long sB, long long sC,
                  long long sBias, long long sRes) {
    int z = blockIdx.z;
    A  += (size_t)z * sA;
    Bm += (size_t)z * sB;
    C  += (size_t)z * sC;
    if (bias)     bias     += (size_t)z * sBias;
    if (residual) residual += (size_t)z * sRes;

    __shared__ float As[2][GBK][GBM];
    __shared__ float Bs[2][GBK][GBN];

    int tid = threadIdx.x;
    int bm = blockIdx.y * GBM;
    int bn = blockIdx.x * GBN;

    int arow = tid >> 1;            // 0..127
    int acol = (tid & 1) * 4;       // 0 or 4
    int brow = tid >> 5;            // 0..7
    int bcol = (tid & 31) * 4;      // 0..124

    int row_t = (tid >> 4) * 8;
    int col_t = (tid & 15) * 8;

    float acc[8][8];
    #pragma unroll
    for (int i = 0; i < 8; ++i)
        #pragma unroll
        for (int j = 0; j < 8; ++j) acc[i][j] = 0.0f;

    int ntiles = K / GBK;
    float4 aReg, bReg;

    // prefetch tile 0
    aReg = *(const float4*)(A + (size_t)(bm + arow) * K + acol);
    if (bn + bcol < N) bReg = *(const float4*)(Bm + (size_t)brow * N + bn + bcol);
    else               bReg = make_float4(0.f, 0.f, 0.f, 0.f);
    As[0][acol + 0][arow] = aReg.x;
    As[0][acol + 1][arow] = aReg.y;
    As[0][acol + 2][arow] = aReg.z;
    As[0][acol + 3][arow] = aReg.w;
    *(float4*)&Bs[0][brow][bcol] = bReg;
    __syncthreads();

    int buf = 0;
    for (int kt = 0; kt < ntiles; ++kt) {
        int knext = (kt + 1) * GBK;
        if (kt + 1 < ntiles) {
            aReg = *(const float4*)(A + (size_t)(bm + arow) * K + knext + acol);
            if (bn + bcol < N) bReg = *(const float4*)(Bm + (size_t)(knext + brow) * N + bn + bcol);
            else               bReg = make_float4(0.f, 0.f, 0.f, 0.f);
        }
        #pragma unroll
        for (int k = 0; k < GBK; ++k) {
            float a[8], b[8];
            *(float4*)&a[0] = *(const float4*)&As[buf][k][row_t];
            *(float4*)&a[4] = *(const float4*)&As[buf][k][row_t + 4];
            *(float4*)&b[0] = *(const float4*)&Bs[buf][k][col_t];
            *(float4*)&b[4] = *(const float4*)&Bs[buf][k][col_t + 4];
            #pragma unroll
            for (int i = 0; i < 8; ++i)
                #pragma unroll
                for (int j = 0; j < 8; ++j)
                    acc[i][j] += a[i] * b[j];
        }
        if (kt + 1 < ntiles) {
            int nb = buf ^ 1;
            As[nb][acol + 0][arow] = aReg.x;
            As[nb][acol + 1][arow] = aReg.y;
            As[nb][acol + 2][arow] = aReg.z;
            As[nb][acol + 3][arow] = aReg.w;
            *(float4*)&Bs[nb][brow][bcol] = bReg;
            __syncthreads();
            buf = nb;
        }
    }

    // epilogue
    #pragma unroll
    for (int i = 0; i < 8; ++i) {
        int m = bm + row_t + i;
        if (m >= M) continue;
        long long orow = m;
        if (kv_pad) orow = (long long)m + (long long)kv_pad * (m / seg_rows + 1);
        #pragma unroll
        for (int jg = 0; jg < 2; ++jg) {
            int n = bn + col_t + jg * 4;
            if (n >= N) continue;
            float4 v = make_float4(alpha * acc[i][jg * 4 + 0],
                                   alpha * acc[i][jg * 4 + 1],
                                   alpha * acc[i][jg * 4 + 2],
                                   alpha * acc[i][jg * 4 + 3]);
            if (bias) {
                float4 bv = *(const float4*)(bias + n);
                v.x += bv.x; v.y += bv.y; v.z += bv.z; v.w += bv.w;
            }
            if (do_gelu) {
                v.x = gelu_f(v.x); v.y = gelu_f(v.y);
                v.z = gelu_f(v.z); v.w = gelu_f(v.w);
            }
            if (residual) {
                float4 rv = *(const float4*)(residual + (size_t)m * N + n);
                v.x += rv.x; v.y += rv.y; v.z += rv.z; v.w += rv.w;
            }
            float* cp = C + (size_t)orow * N + n;
            if (accumulate) {
                float4 cv = *(const float4*)cp;
                v.x += cv.x; v.y += cv.y; v.z += cv.z; v.w += cv.w;
            }
            *(float4*)cp = v;
        }
    }
}

// ---------------- relative position bias table: tab[h][rel] ----------------
__global__ void biastab_kernel(const float* __restrict__ relpos, float* __restrict__ tab) {
    int idx = blockIdx.x * 256 + threadIdx.x;
    if (idx >= H_ * L_) return;
    int h = idx / L_, rel = idx % L_;
    int bucket;
    if (rel < 16) {
        bucket = rel;
    } else {
        // 16 + floor( log(rel/16) / log(8) * 16 ), clamped to 31
        float lg = logf((float)rel * (1.0f / 16.0f)) * (16.0f / 2.0794415416798357f);
        bucket = 16 + (int)lg;
        if (bucket > 31) bucket = 31;
    }
    tab[idx] = relpos[h * NB_ + bucket];
}

// ---------------- prefix KV copy into concat buffers ----------------
__global__ void prefix_kernel(const float* __restrict__ pk, const float* __restrict__ pv,
                              float* __restrict__ kc, float* __restrict__ vc, int sel) {
    int b = blockIdx.y;
    int i = blockIdx.x * 256 + threadIdx.x;
    if (i >= P_ * D_) return;
    size_t src = ((size_t)(b * 2 + sel)) * (P_ * D_) + i;
    size_t dst = (size_t)b * LK_ * D_ + i;
    kc[dst] = pk[src];
    vc[dst] = pv[src];
}

// ---------------- flash attention: 64-query tile, quad-per-query, online softmax -------
// Q pre-scaled by HD^-0.5. Kc/Vc are [B, LK, H*HD] (prefix prepended).
// CAUSAL: prefix keys (j < P) always visible, no bias; real keys causal + bias table.
#define ATTN_SMEM ((3 * 64 * 68 + 1024) * 4)

template <bool CAUSAL>
__global__ __launch_bounds__(256)
void attn_kernel(const float* __restrict__ Q, const float* __restrict__ Kc,
                 const float* __restrict__ Vc, float* __restrict__ O,
                 const float* __restrict__ btab) {
    extern __shared__ float sm[];
    float* Qs  = sm;                 // [64][68]
    float* Ks  = Qs + 64 * 68;       // [64][68]
    float* Vs  = Ks + 64 * 68;       // [64][68]
    float* bsh = Vs + 64 * 68;       // [1024]

    int q0 = blockIdx.x * 64;
    int h  = blockIdx.y;
    int b  = blockIdx.z;
    int tid  = threadIdx.x;
    int lane = tid & 31;
    int qi   = tid >> 2;             // 0..63
    int sub  = tid & 3;              // 0..3

    const float* Qb = Q  + (size_t)(b * L_)  * D_ + h * HD_;
    const float* Kb = Kc + (size_t)(b * LK_) * D_ + h * HD_;
    const float* Vb = Vc + (size_t)(b * LK_) * D_ + h * HD_;

    // load Q tile
    for (int idx = tid; idx < 64 * 16; idx += 256) {
        int r = idx >> 4, c4 = idx & 15;
        float4 v = *(const float4*)(Qb + (size_t)(q0 + r) * D_ + c4 * 4);
        *(float4*)&Qs[r * 68 + c4 * 4] = v;
    }
    if (CAUSAL) {
        for (int i = tid; i < L_; i += 256) bsh[i] = btab[h * L_ + i];
    }

    float mrun = -1e30f, lrun = 0.0f;
    float4 o4[4];
    #pragma unroll
    for (int c = 0; c < 4; ++c) o4[c] = make_float4(0.f, 0.f, 0.f, 0.f);

    int qpos = q0 + qi;
    int ntiles = (LK_ + 63) / 64;
    if (CAUSAL) {
        int need = (P_ + q0 + 63) / 64 + 1;
        if (need < ntiles) ntiles = need;
    }

    for (int kt = 0; kt < ntiles; ++kt) {
        int k0 = kt * 64;
        __syncthreads();  // protect Ks/Vs reuse (also orders first Qs/bsh fill)
        for (int idx = tid; idx < 64 * 16; idx += 256) {
            int r = idx >> 4, c4 = idx & 15;
            int j = k0 + r;
            float4 kv, vv;
            if (j < LK_) {
                kv = *(const float4*)(Kb + (size_t)j * D_ + c4 * 4);
                vv = *(const float4*)(Vb + (size_t)j * D_ + c4 * 4);
            } else {
                kv = make_float4(0.f, 0.f, 0.f, 0.f);
                vv = kv;
            }
            *(float4*)&Ks[r * 68 + c4 * 4] = kv;
            *(float4*)&Vs[r * 68 + c4 * 4] = vv;
        }
        __syncthreads();

        float s[16];
        #pragma unroll
        for (int kk = 0; kk < 16; ++kk) s[kk] = 0.0f;
        const float4* Qrow = (const float4*)&Qs[qi * 68];
        #pragma unroll
        for (int d4 = 0; d4 < 16; ++d4) {
            float4 qv = Qrow[d4];
            #pragma unroll
            for (int kk = 0; kk < 16; ++kk) {
                float4 kv = *(const float4*)&Ks[(kk * 4 + sub) * 68 + d4 * 4];
                s[kk] += qv.x * kv.x + qv.y * kv.y + qv.z * kv.z + qv.w * kv.w;
            }
        }
        // mask + bias
        #pragma unroll
        for (int kk = 0; kk < 16; ++kk) {
            int j = k0 + kk * 4 + sub;
            bool valid = (j < LK_);
            if (CAUSAL) {
                if (j >= P_) {
                    int kp = j - P_;
                    if (kp > qpos) valid = false;
                    else s[kk] += bsh[qpos - kp];
                }
            }
            if (!valid) s[kk] = -1e30f;
        }
        // online softmax (quad = 4 threads share one query)
        float tmax = s[0];
        #pragma unroll
        for (int kk = 1; kk < 16; ++kk) tmax = fmaxf(tmax, s[kk]);
        tmax = fmaxf(tmax, __shfl_xor_sync(0xffffffffu, tmax, 1));
        tmax = fmaxf(tmax, __shfl_xor_sync(0xffffffffu, tmax, 2));
        float mnew = fmaxf(mrun, tmax);
        float corr = __expf(mrun - mnew);
        lrun *= corr;
        #pragma unroll
        for (int c = 0; c < 4; ++c) {
            o4[c].x *= corr; o4[c].y *= corr; o4[c].z *= corr; o4[c].w *= corr;
        }
        float p[16];
        float ps = 0.0f;
        #pragma unroll
        for (int kk = 0; kk < 16; ++kk) { p[kk] = __expf(s[kk] - mnew); ps += p[kk]; }
        ps += __shfl_xor_sync(0xffffffffu, ps, 1);
        ps += __shfl_xor_sync(0xffffffffu, ps, 2);
        lrun += ps;
        mrun = mnew;
        // P*V: exchange p across quad, accumulate thread's 16 output columns
        int base = lane & ~3;
        #pragma unroll
        for (int kk = 0; kk < 16; ++kk) {
            #pragma unroll
            for (int src = 0; src < 4; ++src) {
                float pj = __shfl_sync(0xffffffffu, p[kk], base + src);
                const float4* vr = (const float4*)&Vs[(kk * 4 + src) * 68 + sub * 16];
                #pragma unroll
                for (int c = 0; c < 4; ++c) {
                    float4 vv = vr[c];
                    o4[c].x += pj * vv.x; o4[c].y += pj * vv.y;
                    o4[c].z += pj * vv.z; o4[c].w += pj * vv.w;
                }
            }
        }
    }

    float inv = 1.0f / lrun;
    float* Op = O + (size_t)(b * L_ + q0 + qi) * D_ + h * HD_ + sub * 16;
    #pragma unroll
    for (int c = 0; c < 4; ++c) {
        float4 v = o4[c];
        v.x *= inv; v.y *= inv; v.z *= inv; v.w *= inv;
        *(float4*)(Op + c * 4) = v;
    }
}

// ---------------- gated gelu: g = gelu(h0) * h1 ----------------
__global__ void gate_kernel(const float* __restrict__ h0, const float* __restrict__ h1,
                            float* __restrict__ g, int n4) {
    int i = blockIdx.x * 256 + threadIdx.x;
    if (i >= n4) return;
    float4 a = ((const float4*)h0)[i];
    float4 b = ((const float4*)h1)[i];
    float4 r = make_float4(gelu_f(a.x) * b.x, gelu_f(a.y) * b.y,
                           gelu_f(a.z) * b.z, gelu_f(a.w) * b.w);
    ((float4*)g)[i] = r;
}

// ---------------- host side ----------------
static void gemm(const float* A, const float* Bm, float* C, int M, int N, int K,
                 float alpha, const float* bias, const float* residual,
                 int do_gelu, int accumulate, int kv_pad, int seg_rows,
                 long long sA, long long sB, long long sC,
                 long long sBias, long long sRes, int batches) {
    dim3 grid((N + GBN - 1) / GBN, (M + GBM - 1) / GBM, batches);
    sgemm_kernel<<<grid, 256>>>(A, Bm, C, M, N, K, alpha, bias, residual,
                                do_gelu, accumulate, kv_pad, seg_rows,
                                sA, sB, sC, sBias, sRes);
}

extern "C" void kernel_launch(void* const* d_in, const int* in_sizes, int n_in,
                              void* d_out, int out_size) {
    const float* inputs  = (const float*)d_in[0];
    const float* encoded = (const float*)d_in[1];
    const float* awd     = (const float*)d_in[2];
    const float* awu     = (const float*)d_in[3];
    const float* abd     = (const float*)d_in[4];
    const float* abu     = (const float*)d_in[5];
    const float* pk      = (const float*)d_in[6];
    const float* pv      = (const float*)d_in[7];
    const float* ln1     = (const float*)d_in[8];
    const float* ln2     = (const float*)d_in[9];
    const float* ln3     = (const float*)d_in[10];
    const float* sa_wq   = (const float*)d_in[11];
    const float* sa_wk   = (const float*)d_in[12];
    const float* sa_wv   = (const float*)d_in[13];
    const float* sa_wo   = (const float*)d_in[14];
    const float* ca_wq   = (const float*)d_in[15];
    const float* ca_wk   = (const float*)d_in[16];
    const float* ca_wv   = (const float*)d_in[17];
    const float* ca_wo   = (const float*)d_in[18];
    const float* relpos  = (const float*)d_in[19];
    const float* wi0     = (const float*)d_in[20];
    const float* wi1     = (const float*)d_in[21];
    const float* wo      = (const float*)d_in[22];
    // d_in[23] decoder_mask (causal tril) and d_in[24] encoder_decoder_mask (all true)
    // are applied structurally in the attention kernel.
    float* out = (float*)d_out;

    float *xn, *q, *kc, *vc, *o, *x, *y, *h0, *h1, *az, *bt;
    cudaGetSymbolAddress((void**)&xn, g_xn);
    cudaGetSymbolAddress((void**)&q,  g_q);
    cudaGetSymbolAddress((void**)&kc, g_kc);
    cudaGetSymbolAddress((void**)&vc, g_vc);
    cudaGetSymbolAddress((void**)&o,  g_o);
    cudaGetSymbolAddress((void**)&x,  g_x);
    cudaGetSymbolAddress((void**)&y,  g_y);
    cudaGetSymbolAddress((void**)&h0, g_h0);
    cudaGetSymbolAddress((void**)&h1, g_h1);
    cudaGetSymbolAddress((void**)&az, g_az);
    cudaGetSymbolAddress((void**)&bt, g_bt);

    cudaFuncSetAttribute(attn_kernel<true>,  cudaFuncAttributeMaxDynamicSharedMemorySize, ATTN_SMEM);
    cudaFuncSetAttribute(attn_kernel<false>, cudaFuncAttributeMaxDynamicSharedMemorySize, ATTN_SMEM);

    const float qscale = 0.125f;   // HD^-0.5

    // ---- self attention ----
    rmsnorm_kernel<<<M_, 256>>>(inputs, ln1, xn);
    gemm(xn, sa_wq, q,  M_, D_, D_, qscale, 0, 0, 0, 0, 0, 0,  0, 0, 0, 0, 0, 1);
    gemm(xn, sa_wk, kc, M_, D_, D_, 1.0f,   0, 0, 0, 0, P_, L_, 0, 0, 0, 0, 0, 1);
    gemm(xn, sa_wv, vc, M_, D_, D_, 1.0f,   0, 0, 0, 0, P_, L_, 0, 0, 0, 0, 0, 1);
    prefix_kernel<<<dim3((P_ * D_ + 255) / 256, B_), 256>>>(pk, pv, kc, vc, 0);
    biastab_kernel<<<(H_ * L_ + 255) / 256, 256>>>(relpos, bt);
    attn_kernel<true><<<dim3(L_ / 64, H_, B_), 256, ATTN_SMEM>>>(q, kc, vc, o, bt);
    gemm(o, sa_wo, x, M_, D_, D_, 1.0f, 0, inputs, 0, 0, 0, 0, 0, 0, 0, 0, 0, 1);

    // ---- cross attention ----
    rmsnorm_kernel<<<M_, 256>>>(x, ln2, xn);
    gemm(xn,      ca_wq, q,  M_, D_, D_, qscale, 0, 0, 0, 0, 0, 0,  0, 0, 0, 0, 0, 1);
    gemm(encoded, ca_wk, kc, M_, D_, D_, 1.0f,   0, 0, 0, 0, P_, L_, 0, 0, 0, 0, 0, 1);
    gemm(encoded, ca_wv, vc, M_, D_, D_, 1.0f,   0, 0, 0, 0, P_, L_, 0, 0, 0, 0, 0, 1);
    prefix_kernel<<<dim3((P_ * D_ + 255) / 256, B_), 256>>>(pk, pv, kc, vc, 1);
    attn_kernel<false><<<dim3(L_ / 64, H_, B_), 256, ATTN_SMEM>>>(q, kc, vc, o, 0);
    gemm(o, ca_wo, y, M_, D_, D_, 1.0f, 0, x, 0, 0, 0, 0, 0, 0, 0, 0, 0, 1);

    // ---- MLP + adapter ----
    rmsnorm_kernel<<<M_, 256>>>(y, ln3, xn);   // xn = lz
    gemm(xn, wi0, h0, M_, F_, D_, 1.0f, 0, 0, 0, 0, 0, 0, 0, 0, 0, 0, 0, 1);
    gemm(xn, wi1, h1, M_, F_, D_, 1.0f, 0, 0, 0, 0, 0, 0, 0, 0, 0, 0, 0, 1);
    gate_kernel<<<((M_ * (F_ / 4)) + 255) / 256, 256>>>(h0, h1, h0, M_ * (F_ / 4));
    gemm(h0, wo, out, M_, D_, F_, 1.0f, 0, y, 0, 0, 0, 0, 0, 0, 0, 0, 0, 1);

    // adapter: az = gelu(lz @ wd + bd);  out += az @ wu + bu
    gemm(xn, awd, az, L_, A_, D_, 1.0f, abd, 0, 1, 0, 0, 0,
         (long long)L_ * D_, (long long)D_ * A_, (long long)L_ * A_, A_, 0, B_);
    gemm(az, awu, out, L_, D_, A_, 1.0f, abu, 0, 0, 1, 0, 0,
         (long long)L_ * A_, (long long)A_ * D_, (long long)L_ * D_, D_, 0, B_);
}

// round 2
// speedup vs baseline: 3.8028x; 3.8028x over previous
#include <cuda_runtime.h>
#include <math.h>

#define D_  1024
#define H_  16
#define HD_ 64
#define F_  2816
#define A_  64
#define P_  30
#define NB_ 32
#define B_  4
#define L_  1024
#define LK_ 1054            // P_ + L_
#define M_  4096            // B_ * L_

// ---------------- scratch (device globals; no runtime allocation) ----------------
__device__ float g_xn[M_ * D_];
__device__ float g_q [M_ * D_];
__device__ float g_kc[B_ * LK_ * D_];
__device__ float g_vc[B_ * LK_ * D_];
__device__ float g_o [M_ * D_];
__device__ float g_x [M_ * D_];
__device__ float g_y [M_ * D_];
__device__ float g_h0[(size_t)M_ * F_];
__device__ float g_h1[(size_t)M_ * F_];
__device__ float g_az[B_ * L_ * A_];
__device__ float g_bt[H_ * L_];

// ---------------- helpers ----------------
__device__ __forceinline__ float gelu_f(float x) {
    const float c = 0.7978845608028654f;       // sqrt(2/pi)
    float t = tanhf(c * (x + 0.044715f * x * x * x));
    return 0.5f * x * (1.0f + t);
}

__device__ __forceinline__ unsigned f2tf(float f) {
    unsigned u;
    asm("cvt.rna.tf32.f32 %0, %1;" : "=r"(u) : "f"(f));
    return u;
}

__device__ __forceinline__ void mma8(float* c, const unsigned* a, unsigned b0, unsigned b1) {
    asm volatile(
        "mma.sync.aligned.m16n8k8.row.col.f32.tf32.tf32.f32 "
        "{%0,%1,%2,%3},{%4,%5,%6,%7},{%8,%9},{%0,%1,%2,%3};"
        : "+f"(c[0]), "+f"(c[1]), "+f"(c[2]), "+f"(c[3])
        : "r"(a[0]), "r"(a[1]), "r"(a[2]), "r"(a[3]), "r"(b0), "r"(b1));
}

// ---------------- rmsnorm ----------------
__global__ void rmsnorm_kernel(const float* __restrict__ x,
                               const float* __restrict__ sc,
                               float* __restrict__ out) {
    int row = blockIdx.x;
    int t = threadIdx.x;
    const float4* xr = (const float4*)(x + (size_t)row * D_);
    float4 v = xr[t];
    float ss = v.x * v.x + v.y * v.y + v.z * v.z + v.w * v.w;
    #pragma unroll
    for (int o = 16; o; o >>= 1) ss += __shfl_xor_sync(0xffffffffu, ss, o);
    __shared__ float sred[8];
    if ((t & 31) == 0) sred[t >> 5] = ss;
    __syncthreads();
    if (t < 8) {
        float s2 = sred[t];
        #pragma unroll
        for (int o = 4; o; o >>= 1) s2 += __shfl_xor_sync(0xffu, s2, o);
        if (t == 0) sred[0] = s2;
    }
    __syncthreads();
    float inv = rsqrtf(sred[0] * (1.0f / D_) + 1e-6f);
    float4 sv = ((const float4*)sc)[t];
    float4 ov = make_float4(v.x * inv * sv.x, v.y * inv * sv.y,
                            v.z * inv * sv.z, v.w * inv * sv.w);
    ((float4*)(out + (size_t)row * D_))[t] = ov;
}

// ---------------- tf32 tensor-core GEMM ----------------
// C = alpha*A*B (+bias)(gelu)(+residual)(+=C). A[M,K], B[K,N] row-major fp32.
// M multiple of 128, K multiple of 16, N multiple of 8 (guarded vs tile).
#define GBM 128
#define GBN 128
#define GBK 16
#define ASTR 20
#define BSTR 136

__global__ __launch_bounds__(256, 2)
void gemm_tf32_kernel(const float* __restrict__ A, const float* __restrict__ Bm,
                      float* __restrict__ C, int M, int N, int K,
                      float alpha,
                      const float* __restrict__ bias,
                      const float* __restrict__ residual,
                      int do_gelu, int accumulate, int kv_pad, int seg_rows,
                      long long sA, long long sB, long long sC,
                      long long sBias, long long sRes) {
    int z = blockIdx.z;
    A  += (size_t)z * sA;
    Bm += (size_t)z * sB;
    C  += (size_t)z * sC;
    if (bias)     bias     += (size_t)z * sBias;
    if (residual) residual += (size_t)z * sRes;

    __shared__ unsigned As[2][GBM * ASTR];
    __shared__ unsigned Bs[2][GBK * BSTR];

    int tid  = threadIdx.x;
    int lane = tid & 31;
    int wid  = tid >> 5;
    int grpr = lane >> 2;
    int grpc = lane & 3;
    int warp_m = (wid & 1) * 64;
    int warp_n = (wid >> 1) * 32;
    int bm = blockIdx.y * GBM;
    int bn = blockIdx.x * GBN;

    int ar = tid >> 2;          // A rows ar, ar+64
    int ac = (tid & 3) * 4;     // k offset
    int br = tid >> 5;          // B rows br, br+8
    int bc = (tid & 31) * 4;    // n offset

    float acc[4][4][4];
    #pragma unroll
    for (int i = 0; i < 4; ++i)
        #pragma unroll
        for (int j = 0; j < 4; ++j)
            #pragma unroll
            for (int k = 0; k < 4; ++k) acc[i][j][k] = 0.0f;

    int ntiles = K / GBK;
    float4 aR0, aR1, bR0, bR1;

    // prefetch tile 0
    {
        aR0 = *(const float4*)(A + (size_t)(bm + ar) * K + ac);
        aR1 = *(const float4*)(A + (size_t)(bm + ar + 64) * K + ac);
        if (bn + bc < N) {
            bR0 = *(const float4*)(Bm + (size_t)br * N + bn + bc);
            bR1 = *(const float4*)(Bm + (size_t)(br + 8) * N + bn + bc);
        } else { bR0 = make_float4(0,0,0,0); bR1 = bR0; }
        unsigned* ap = &As[0][ar * ASTR + ac];
        ap[0]=f2tf(aR0.x); ap[1]=f2tf(aR0.y); ap[2]=f2tf(aR0.z); ap[3]=f2tf(aR0.w);
        unsigned* ap2 = &As[0][(ar + 64) * ASTR + ac];
        ap2[0]=f2tf(aR1.x); ap2[1]=f2tf(aR1.y); ap2[2]=f2tf(aR1.z); ap2[3]=f2tf(aR1.w);
        unsigned* bp = &Bs[0][br * BSTR + bc];
        bp[0]=f2tf(bR0.x); bp[1]=f2tf(bR0.y); bp[2]=f2tf(bR0.z); bp[3]=f2tf(bR0.w);
        unsigned* bp2 = &Bs[0][(br + 8) * BSTR + bc];
        bp2[0]=f2tf(bR1.x); bp2[1]=f2tf(bR1.y); bp2[2]=f2tf(bR1.z); bp2[3]=f2tf(bR1.w);
    }
    __syncthreads();

    int buf = 0;
    for (int kt = 0; kt < ntiles; ++kt) {
        int knext = (kt + 1) * GBK;
        if (kt + 1 < ntiles) {
            aR0 = *(const float4*)(A + (size_t)(bm + ar) * K + knext + ac);
            aR1 = *(const float4*)(A + (size_t)(bm + ar + 64) * K + knext + ac);
            if (bn + bc < N) {
                bR0 = *(const float4*)(Bm + (size_t)(knext + br) * N + bn + bc);
                bR1 = *(const float4*)(Bm + (size_t)(knext + br + 8) * N + bn + bc);
            } else { bR0 = make_float4(0,0,0,0); bR1 = bR0; }
        }
        // compute on buf
        #pragma unroll
        for (int ks = 0; ks < 2; ++ks) {
            unsigned af[4][4];
            #pragma unroll
            for (int ma = 0; ma < 4; ++ma) {
                int m = warp_m + ma * 16 + grpr;
                int c = ks * 8 + grpc;
                af[ma][0] = As[buf][m * ASTR + c];
                af[ma][1] = As[buf][(m + 8) * ASTR + c];
                af[ma][2] = As[buf][m * ASTR + c + 4];
                af[ma][3] = As[buf][(m + 8) * ASTR + c + 4];
            }
            #pragma unroll
            for (int na = 0; na < 4; ++na) {
                int n = warp_n + na * 8 + grpr;
                unsigned b0 = Bs[buf][(ks * 8 + grpc) * BSTR + n];
                unsigned b1 = Bs[buf][(ks * 8 + grpc + 4) * BSTR + n];
                #pragma unroll
                for (int ma = 0; ma < 4; ++ma)
                    mma8(acc[ma][na], af[ma], b0, b1);
            }
        }
        if (kt + 1 < ntiles) {
            int nb = buf ^ 1;
            unsigned* ap = &As[nb][ar * ASTR + ac];
            ap[0]=f2tf(aR0.x); ap[1]=f2tf(aR0.y); ap[2]=f2tf(aR0.z); ap[3]=f2tf(aR0.w);
            unsigned* ap2 = &As[nb][(ar + 64) * ASTR + ac];
            ap2[0]=f2tf(aR1.x); ap2[1]=f2tf(aR1.y); ap2[2]=f2tf(aR1.z); ap2[3]=f2tf(aR1.w);
            unsigned* bp = &Bs[nb][br * BSTR + bc];
            bp[0]=f2tf(bR0.x); bp[1]=f2tf(bR0.y); bp[2]=f2tf(bR0.z); bp[3]=f2tf(bR0.w);
            unsigned* bp2 = &Bs[nb][(br + 8) * BSTR + bc];
            bp2[0]=f2tf(bR1.x); bp2[1]=f2tf(bR1.y); bp2[2]=f2tf(bR1.z); bp2[3]=f2tf(bR1.w);
            __syncthreads();
            buf = nb;
        }
    }

    // epilogue: element pairs at (m, n), (m, n+1)
    #pragma unroll
    for (int ma = 0; ma < 4; ++ma) {
        #pragma unroll
        for (int na = 0; na < 4; ++na) {
            int n = bn + warp_n + na * 8 + 2 * grpc;
            if (n >= N) continue;
            #pragma unroll
            for (int half = 0; half < 2; ++half) {
                int m = bm + warp_m + ma * 16 + grpr + half * 8;
                float v0 = alpha * acc[ma][na][half * 2 + 0];
                float v1 = alpha * acc[ma][na][half * 2 + 1];
                if (bias) { v0 += bias[n]; v1 += bias[n + 1]; }
                if (do_gelu) { v0 = gelu_f(v0); v1 = gelu_f(v1); }
                if (residual) {
                    float2 rv = *(const float2*)(residual + (size_t)m * N + n);
                    v0 += rv.x; v1 += rv.y;
                }
                long long orow = m;
                if (kv_pad) orow = (long long)m + (long long)kv_pad * (m / seg_rows + 1);
                float* cp = C + (size_t)orow * N + n;
                if (accumulate) {
                    float2 cv = *(const float2*)cp;
                    v0 += cv.x; v1 += cv.y;
                }
                *(float2*)cp = make_float2(v0, v1);
            }
        }
    }
}

// ---------------- relative position bias table ----------------
__global__ void biastab_kernel(const float* __restrict__ relpos, float* __restrict__ tab) {
    int idx = blockIdx.x * 256 + threadIdx.x;
    if (idx >= H_ * L_) return;
    int h = idx / L_, rel = idx % L_;
    int bucket;
    if (rel < 16) {
        bucket = rel;
    } else {
        float lg = logf((float)rel * (1.0f / 16.0f)) * (16.0f / 2.0794415416798357f);
        bucket = 16 + (int)lg;
        if (bucket > 31) bucket = 31;
    }
    tab[idx] = relpos[h * NB_ + bucket];
}

// ---------------- prefix KV copy ----------------
__global__ void prefix_kernel(const float* __restrict__ pk, const float* __restrict__ pv,
                              float* __restrict__ kc, float* __restrict__ vc, int sel) {
    int b = blockIdx.y;
    int i = blockIdx.x * 256 + threadIdx.x;
    if (i >= P_ * D_) return;
    size_t src = ((size_t)(b * 2 + sel)) * (P_ * D_) + i;
    size_t dst = (size_t)b * LK_ * D_ + i;
    kc[dst] = pk[src];
    vc[dst] = pv[src];
}

// ---------------- tensor-core flash attention ----------------
// 64-query tile, 4 warps (16 rows each), tf32 mma, online softmax.
// smem: Ks[64][68] + Vs[64][72] + Ps[64][68] (tf32 bits) + bias[1024]
#define ATTN_SMEM_TC ((64 * 68 + 64 * 72 + 64 * 68) * 4 + L_ * 4)

template <bool CAUSAL>
__global__ __launch_bounds__(128)
void attn_tc_kernel(const float* __restrict__ Q, const float* __restrict__ Kc,
                    const float* __restrict__ Vc, float* __restrict__ O,
                    const float* __restrict__ btab) {
    extern __shared__ unsigned smu[];
    unsigned* Ks = smu;                      // [64][68]
    unsigned* Vs = Ks + 64 * 68;             // [64][72]
    unsigned* Ps = Vs + 64 * 72;             // [64][68]
    float* bsh = (float*)(Ps + 64 * 68);     // [1024]

    int q0 = blockIdx.x * 64;
    int h  = blockIdx.y;
    int b  = blockIdx.z;
    int tid  = threadIdx.x;
    int w    = tid >> 5;
    int lane = tid & 31;
    int grpr = lane >> 2;
    int grpc = lane & 3;

    const float* Qb = Q  + (size_t)(b * L_)  * D_ + h * HD_;
    const float* Kb = Kc + (size_t)(b * LK_) * D_ + h * HD_;
    const float* Vb = Vc + (size_t)(b * LK_) * D_ + h * HD_;

    // stage Q (tf32) into Ks, then pull fragments into registers
    for (int i = tid; i < 64 * 16; i += 128) {
        int r = i >> 4, c4 = i & 15;
        float4 v = *(const float4*)(Qb + (size_t)(q0 + r) * D_ + c4 * 4);
        unsigned* p = &Ks[r * 68 + c4 * 4];
        p[0] = f2tf(v.x); p[1] = f2tf(v.y); p[2] = f2tf(v.z); p[3] = f2tf(v.w);
    }
    if (CAUSAL) {
        for (int i = tid; i < L_; i += 128) bsh[i] = btab[h * L_ + i];
    }
    __syncthreads();

    unsigned qa[8][4];
    #pragma unroll
    for (int ks = 0; ks < 8; ++ks) {
        int r = w * 16 + grpr, c = ks * 8 + grpc;
        qa[ks][0] = Ks[r * 68 + c];
        qa[ks][1] = Ks[(r + 8) * 68 + c];
        qa[ks][2] = Ks[r * 68 + c + 4];
        qa[ks][3] = Ks[(r + 8) * 68 + c + 4];
    }

    float m0r = -1e30f, m1r = -1e30f, l0 = 0.0f, l1 = 0.0f;
    float oacc[8][4];
    #pragma unroll
    for (int na = 0; na < 8; ++na)
        #pragma unroll
        for (int k = 0; k < 4; ++k) oacc[na][k] = 0.0f;

    int r0g = q0 + w * 16 + grpr;
    int r1g = r0g + 8;

    int ntiles = (LK_ + 63) / 64;
    if (CAUSAL) {
        int need = blockIdx.x + 2;
        if (need < ntiles) ntiles = need;
    }

    for (int kt = 0; kt < ntiles; ++kt) {
        int k0 = kt * 64;
        __syncthreads();
        for (int i = tid; i < 64 * 16; i += 128) {
            int r = i >> 4, c4 = i & 15;
            int j = k0 + r;
            float4 kv, vv;
            if (j < LK_) {
                kv = *(const float4*)(Kb + (size_t)j * D_ + c4 * 4);
                vv = *(const float4*)(Vb + (size_t)j * D_ + c4 * 4);
            } else {
                kv = make_float4(0.f, 0.f, 0.f, 0.f);
                vv = kv;
            }
            unsigned* kp = &Ks[r * 68 + c4 * 4];
            kp[0] = f2tf(kv.x); kp[1] = f2tf(kv.y); kp[2] = f2tf(kv.z); kp[3] = f2tf(kv.w);
            unsigned* vp = &Vs[r * 72 + c4 * 4];
            vp[0] = f2tf(vv.x); vp[1] = f2tf(vv.y); vp[2] = f2tf(vv.z); vp[3] = f2tf(vv.w);
        }
        __syncthreads();

        // S = Q K^T
        float sacc[8][4];
        #pragma unroll
        for (int na = 0; na < 8; ++na)
            #pragma unroll
            for (int k = 0; k < 4; ++k) sacc[na][k] = 0.0f;
        #pragma unroll
        for (int ks = 0; ks < 8; ++ks) {
            #pragma unroll
            for (int na = 0; na < 8; ++na) {
                unsigned b0 = Ks[(na * 8 + grpr) * 68 + ks * 8 + grpc];
                unsigned b1 = Ks[(na * 8 + grpr) * 68 + ks * 8 + grpc + 4];
                mma8(sacc[na], qa[ks], b0, b1);
            }
        }

        // mask + bias, row max
        float rm0 = -1e30f, rm1 = -1e30f;
        #pragma unroll
        for (int na = 0; na < 8; ++na) {
            int j0 = k0 + na * 8 + 2 * grpc;
            int j1 = j0 + 1;
            if (CAUSAL) {
                if (j0 >= P_) {
                    int kp = j0 - P_;
                    if (kp > r0g) sacc[na][0] = -1e30f; else sacc[na][0] += bsh[r0g - kp];
                    if (kp > r1g) sacc[na][2] = -1e30f; else sacc[na][2] += bsh[r1g - kp];
                }
                if (j1 >= P_) {
                    int kp = j1 - P_;
                    if (kp > r0g) sacc[na][1] = -1e30f; else sacc[na][1] += bsh[r0g - kp];
                    if (kp > r1g) sacc[na][3] = -1e30f; else sacc[na][3] += bsh[r1g - kp];
                }
            } else {
                if (j0 >= LK_) { sacc[na][0] = -1e30f; sacc[na][2] = -1e30f; }
                if (j1 >= LK_) { sacc[na][1] = -1e30f; sacc[na][3] = -1e30f; }
            }
            rm0 = fmaxf(rm0, fmaxf(sacc[na][0], sacc[na][1]));
            rm1 = fmaxf(rm1, fmaxf(sacc[na][2], sacc[na][3]));
        }
        rm0 = fmaxf(rm0, __shfl_xor_sync(0xffffffffu, rm0, 1));
        rm0 = fmaxf(rm0, __shfl_xor_sync(0xffffffffu, rm0, 2));
        rm1 = fmaxf(rm1, __shfl_xor_sync(0xffffffffu, rm1, 1));
        rm1 = fmaxf(rm1, __shfl_xor_sync(0xffffffffu, rm1, 2));

        float mn0 = fmaxf(m0r, rm0);
        float mn1 = fmaxf(m1r, rm1);
        float cf0 = __expf(m0r - mn0);
        float cf1 = __expf(m1r - mn1);
        l0 *= cf0; l1 *= cf1;
        m0r = mn0; m1r = mn1;
        #pragma unroll
        for (int na = 0; na < 8; ++na) {
            oacc[na][0] *= cf0; oacc[na][1] *= cf0;
            oacc[na][2] *= cf1; oacc[na][3] *= cf1;
        }

        float ps0 = 0.0f, ps1 = 0.0f;
        int pr = w * 16 + grpr;
        #pragma unroll
        for (int na = 0; na < 8; ++na) {
            float p0 = __expf(sacc[na][0] - mn0);
            float p1 = __expf(sacc[na][1] - mn0);
            float p2 = __expf(sacc[na][2] - mn1);
            float p3 = __expf(sacc[na][3] - mn1);
            ps0 += p0 + p1;
            ps1 += p2 + p3;
            uint2 u01; u01.x = f2tf(p0); u01.y = f2tf(p1);
            uint2 u23; u23.x = f2tf(p2); u23.y = f2tf(p3);
            *(uint2*)&Ps[pr * 68 + na * 8 + 2 * grpc]       = u01;
            *(uint2*)&Ps[(pr + 8) * 68 + na * 8 + 2 * grpc] = u23;
        }
        ps0 += __shfl_xor_sync(0xffffffffu, ps0, 1);
        ps0 += __shfl_xor_sync(0xffffffffu, ps0, 2);
        ps1 += __shfl_xor_sync(0xffffffffu, ps1, 1);
        ps1 += __shfl_xor_sync(0xffffffffu, ps1, 2);
        l0 += ps0; l1 += ps1;

        __syncwarp();

        // O += P V
        #pragma unroll
        for (int ks = 0; ks < 8; ++ks) {
            unsigned pa[4];
            int pc = ks * 8 + grpc;
            pa[0] = Ps[pr * 68 + pc];
            pa[1] = Ps[(pr + 8) * 68 + pc];
            pa[2] = Ps[pr * 68 + pc + 4];
            pa[3] = Ps[(pr + 8) * 68 + pc + 4];
            #pragma unroll
            for (int na = 0; na < 8; ++na) {
                unsigned b0 = Vs[(ks * 8 + grpc) * 72 + na * 8 + grpr];
                unsigned b1 = Vs[(ks * 8 + 4 + grpc) * 72 + na * 8 + grpr];
                mma8(oacc[na], pa, b0, b1);
            }
        }
    }

    float inv0 = 1.0f / l0;
    float inv1 = 1.0f / l1;
    float* Ob = O + (size_t)(b * L_) * D_ + h * HD_;
    int qr0 = q0 + w * 16 + grpr;
    #pragma unroll
    for (int na = 0; na < 8; ++na) {
        int d = na * 8 + 2 * grpc;
        *(float2*)(Ob + (size_t)qr0 * D_ + d) =
            make_float2(oacc[na][0] * inv0, oacc[na][1] * inv0);
        *(float2*)(Ob + (size_t)(qr0 + 8) * D_ + d) =
            make_float2(oacc[na][2] * inv1, oacc[na][3] * inv1);
    }
}

// ---------------- gated gelu ----------------
__global__ void gate_kernel(const float* __restrict__ h0, const float* __restrict__ h1,
                            float* __restrict__ g, int n4) {
    int i = blockIdx.x * 256 + threadIdx.x;
    if (i >= n4) return;
    float4 a = ((const float4*)h0)[i];
    float4 b = ((const float4*)h1)[i];
    float4 r = make_float4(gelu_f(a.x) * b.x, gelu_f(a.y) * b.y,
                           gelu_f(a.z) * b.z, gelu_f(a.w) * b.w);
    ((float4*)g)[i] = r;
}

// ---------------- host side ----------------
static void gemm(const float* A, const float* Bm, float* C, int M, int N, int K,
                 float alpha, const float* bias, const float* residual,
                 int do_gelu, int accumulate, int kv_pad, int seg_rows,
                 long long sA, long long sB, long long sC,
                 long long sBias, long long sRes, int batches) {
    dim3 grid((N + GBN - 1) / GBN, (M + GBM - 1) / GBM, batches);
    gemm_tf32_kernel<<<grid, 256>>>(A, Bm, C, M, N, K, alpha, bias, residual,
                                    do_gelu, accumulate, kv_pad, seg_rows,
                                    sA, sB, sC, sBias, sRes);
}

extern "C" void kernel_launch(void* const* d_in, const int* in_sizes, int n_in,
                              void* d_out, int out_size) {
    const float* inputs  = (const float*)d_in[0];
    const float* encoded = (const float*)d_in[1];
    const float* awd     = (const float*)d_in[2];
    const float* awu     = (const float*)d_in[3];
    const float* abd     = (const float*)d_in[4];
    const float* abu     = (const float*)d_in[5];
    const float* pk      = (const float*)d_in[6];
    const float* pv      = (const float*)d_in[7];
    const float* ln1     = (const float*)d_in[8];
    const float* ln2     = (const float*)d_in[9];
    const float* ln3     = (const float*)d_in[10];
    const float* sa_wq   = (const float*)d_in[11];
    const float* sa_wk   = (const float*)d_in[12];
    const float* sa_wv   = (const float*)d_in[13];
    const float* sa_wo   = (const float*)d_in[14];
    const float* ca_wq   = (const float*)d_in[15];
    const float* ca_wk   = (const float*)d_in[16];
    const float* ca_wv   = (const float*)d_in[17];
    const float* ca_wo   = (const float*)d_in[18];
    const float* relpos  = (const float*)d_in[19];
    const float* wi0     = (const float*)d_in[20];
    const float* wi1     = (const float*)d_in[21];
    const float* wo      = (const float*)d_in[22];
    float* out = (float*)d_out;

    float *xn, *q, *kc, *vc, *o, *x, *y, *h0, *h1, *az, *bt;
    cudaGetSymbolAddress((void**)&xn, g_xn);
    cudaGetSymbolAddress((void**)&q,  g_q);
    cudaGetSymbolAddress((void**)&kc, g_kc);
    cudaGetSymbolAddress((void**)&vc, g_vc);
    cudaGetSymbolAddress((void**)&o,  g_o);
    cudaGetSymbolAddress((void**)&x,  g_x);
    cudaGetSymbolAddress((void**)&y,  g_y);
    cudaGetSymbolAddress((void**)&h0, g_h0);
    cudaGetSymbolAddress((void**)&h1, g_h1);
    cudaGetSymbolAddress((void**)&az, g_az);
    cudaGetSymbolAddress((void**)&bt, g_bt);

    cudaFuncSetAttribute(attn_tc_kernel<true>,  cudaFuncAttributeMaxDynamicSharedMemorySize, ATTN_SMEM_TC);
    cudaFuncSetAttribute(attn_tc_kernel<false>, cudaFuncAttributeMaxDynamicSharedMemorySize, ATTN_SMEM_TC);

    const float qscale = 0.125f;   // HD^-0.5

    // ---- self attention ----
    rmsnorm_kernel<<<M_, 256>>>(inputs, ln1, xn);
    gemm(xn, sa_wq, q,  M_, D_, D_, qscale, 0, 0, 0, 0, 0, 0,  0, 0, 0, 0, 0, 1);
    gemm(xn, sa_wk, kc, M_, D_, D_, 1.0f,   0, 0, 0, 0, P_, L_, 0, 0, 0, 0, 0, 1);
    gemm(xn, sa_wv, vc, M_, D_, D_, 1.0f,   0, 0, 0, 0, P_, L_, 0, 0, 0, 0, 0, 1);
    prefix_kernel<<<dim3((P_ * D_ + 255) / 256, B_), 256>>>(pk, pv, kc, vc, 0);
    biastab_kernel<<<(H_ * L_ + 255) / 256, 256>>>(relpos, bt);
    attn_tc_kernel<true><<<dim3(L_ / 64, H_, B_), 128, ATTN_SMEM_TC>>>(q, kc, vc, o, bt);
    gemm(o, sa_wo, x, M_, D_, D_, 1.0f, 0, inputs, 0, 0, 0, 0, 0, 0, 0, 0, 0, 1);

    // ---- cross attention ----
    rmsnorm_kernel<<<M_, 256>>>(x, ln2, xn);
    gemm(xn,      ca_wq, q,  M_, D_, D_, qscale, 0, 0, 0, 0, 0, 0,  0, 0, 0, 0, 0, 1);
    gemm(encoded, ca_wk, kc, M_, D_, D_, 1.0f,   0, 0, 0, 0, P_, L_, 0, 0, 0, 0, 0, 1);
    gemm(encoded, ca_wv, vc, M_, D_, D_, 1.0f,   0, 0, 0, 0, P_, L_, 0, 0, 0, 0, 0, 1);
    prefix_kernel<<<dim3((P_ * D_ + 255) / 256, B_), 256>>>(pk, pv, kc, vc, 1);
    attn_tc_kernel<false><<<dim3(L_ / 64, H_, B_), 128, ATTN_SMEM_TC>>>(q, kc, vc, o, 0);
    gemm(o, ca_wo, y, M_, D_, D_, 1.0f, 0, x, 0, 0, 0, 0, 0, 0, 0, 0, 0, 1);

    // ---- MLP + adapter ----
    rmsnorm_kernel<<<M_, 256>>>(y, ln3, xn);   // xn = lz
    gemm(xn, wi0, h0, M_, F_, D_, 1.0f, 0, 0, 0, 0, 0, 0, 0, 0, 0, 0, 0, 1);
    gemm(xn, wi1, h1, M_, F_, D_, 1.0f, 0, 0, 0, 0, 0, 0, 0, 0, 0, 0, 0, 1);
    gate_kernel<<<((M_ * (F_ / 4)) + 255) / 256, 256>>>(h0, h1, h0, M_ * (F_ / 4));
    gemm(h0, wo, out, M_, D_, F_, 1.0f, 0, y, 0, 0, 0, 0, 0, 0, 0, 0, 0, 1);

    // adapter: az = gelu(lz @ wd + bd);  out += az @ wu + bu
    gemm(xn, awd, az, L_, A_, D_, 1.0f, abd, 0, 1, 0, 0, 0,
         (long long)L_ * D_, (long long)D_ * A_, (long long)L_ * A_, A_, 0, B_);
    gemm(az, awu, out, L_, D_, A_, 1.0f, abu, 0, 0, 1, 0, 0,
         (long long)L_ * A_, (long long)A_ * D_, (long long)L_ * D_, D_, 0, B_);
}